// round 2
// baseline (speedup 1.0000x reference)
#include <cuda_runtime.h>

// HybridSurvivalQ: quantum expval collapses to prod cos(x_q[1..6]+theta[1..6]),
// then 65->32->16->1 MLP with ReLU. One thread handles 2 rows; weights in SMEM,
// consumed via LDS.64 broadcast; math in packed fma.rn.f32x2.

#define TPB 256

__device__ __forceinline__ unsigned long long pack2(float lo, float hi) {
    unsigned long long r;
    asm("mov.b64 %0, {%1, %2};" : "=l"(r) : "f"(lo), "f"(hi));
    return r;
}
__device__ __forceinline__ void unpack2(unsigned long long v, float& lo, float& hi) {
    asm("mov.b64 {%0, %1}, %2;" : "=f"(lo), "=f"(hi) : "l"(v));
}
__device__ __forceinline__ unsigned long long ffma2(unsigned long long a,
                                                    unsigned long long b,
                                                    unsigned long long c) {
    unsigned long long d;
    asm("fma.rn.f32x2 %0, %1, %2, %3;" : "=l"(d) : "l"(a), "l"(b), "l"(c));
    return d;
}

__global__ __launch_bounds__(TPB)
void hybrid_mlp_kernel(const float* __restrict__ x_q,
                       const float* __restrict__ x_c,
                       const float* __restrict__ q_params,
                       const float* __restrict__ W1,
                       const float* __restrict__ b1,
                       const float* __restrict__ W2,
                       const float* __restrict__ b2,
                       const float* __restrict__ W3,
                       const float* __restrict__ b3,
                       float* __restrict__ out,
                       int B)
{
    __shared__ __align__(16) float sW1[65 * 32];
    __shared__ __align__(16) float sW2[32 * 16];
    __shared__ __align__(16) float sW3[16];
    __shared__ __align__(16) float sB1[32];
    __shared__ __align__(16) float sB2[16];
    __shared__ float sQP[8];
    __shared__ float sB3;

    for (int i = threadIdx.x; i < 65 * 32; i += TPB) sW1[i] = W1[i];
    for (int i = threadIdx.x; i < 32 * 16; i += TPB) sW2[i] = W2[i];
    if (threadIdx.x < 16) sW3[threadIdx.x] = W3[threadIdx.x];
    if (threadIdx.x < 32) sB1[threadIdx.x] = b1[threadIdx.x];
    if (threadIdx.x < 16) sB2[threadIdx.x] = b2[threadIdx.x];
    if (threadIdx.x < 7)  sQP[threadIdx.x] = q_params[threadIdx.x];
    if (threadIdx.x == 0) sB3 = b3[0];
    __syncthreads();

    long long gtid = (long long)blockIdx.x * TPB + threadIdx.x;
    int r0 = (int)(gtid * 2);
    if (r0 >= B) return;

    // ---- quantum part: q_out = prod_{q=1..6} cos(x_q[q] + theta[q]) ----
    float qv[2];
#pragma unroll
    for (int r = 0; r < 2; r++) {
        const float* xq = x_q + (long long)(r0 + r) * 7;
        float p = 1.0f;
#pragma unroll
        for (int k = 1; k < 7; k++) p *= cosf(xq[k] + sQP[k]);
        qv[r] = p;
    }

    // ---- layer 1: 65 -> 32 (packed accumulators, 2 rows) ----
    unsigned long long acc0[16], acc1[16];
    const unsigned long long* bb1 = (const unsigned long long*)sB1;
#pragma unroll
    for (int k = 0; k < 16; k++) { acc0[k] = bb1[k]; acc1[k] = bb1[k]; }

    {   // input 0 = q_out
        unsigned long long x0 = pack2(qv[0], qv[0]);
        unsigned long long x1 = pack2(qv[1], qv[1]);
        const unsigned long long* w = (const unsigned long long*)sW1;
#pragma unroll
        for (int k = 0; k < 16; k++) {
            unsigned long long ww = w[k];
            acc0[k] = ffma2(x0, ww, acc0[k]);
            acc1[k] = ffma2(x1, ww, acc1[k]);
        }
    }

    const float4* xc0 = (const float4*)(x_c + (long long)r0 * 64);
    const float4* xc1 = (const float4*)(x_c + (long long)(r0 + 1) * 64);
#pragma unroll 4
    for (int j4 = 0; j4 < 16; j4++) {
        float4 v0 = xc0[j4];
        float4 v1 = xc1[j4];
        float a0[4] = {v0.x, v0.y, v0.z, v0.w};
        float a1[4] = {v1.x, v1.y, v1.z, v1.w};
#pragma unroll
        for (int s = 0; s < 4; s++) {
            int j = 1 + j4 * 4 + s;
            unsigned long long x0 = pack2(a0[s], a0[s]);
            unsigned long long x1 = pack2(a1[s], a1[s]);
            const unsigned long long* w = (const unsigned long long*)(sW1 + j * 32);
#pragma unroll
            for (int k = 0; k < 16; k++) {
                unsigned long long ww = w[k];
                acc0[k] = ffma2(x0, ww, acc0[k]);
                acc1[k] = ffma2(x1, ww, acc1[k]);
            }
        }
    }

    // ---- relu + layer 2: 32 -> 16 ----
    float h0[32], h1[32];
#pragma unroll
    for (int k = 0; k < 16; k++) {
        float lo, hi;
        unpack2(acc0[k], lo, hi);
        h0[2 * k] = fmaxf(lo, 0.0f); h0[2 * k + 1] = fmaxf(hi, 0.0f);
        unpack2(acc1[k], lo, hi);
        h1[2 * k] = fmaxf(lo, 0.0f); h1[2 * k + 1] = fmaxf(hi, 0.0f);
    }

    unsigned long long a20[8], a21[8];
    const unsigned long long* bb2 = (const unsigned long long*)sB2;
#pragma unroll
    for (int k = 0; k < 8; k++) { a20[k] = bb2[k]; a21[k] = bb2[k]; }

#pragma unroll
    for (int j = 0; j < 32; j++) {
        unsigned long long x0 = pack2(h0[j], h0[j]);
        unsigned long long x1 = pack2(h1[j], h1[j]);
        const unsigned long long* w = (const unsigned long long*)(sW2 + j * 16);
#pragma unroll
        for (int k = 0; k < 8; k++) {
            unsigned long long ww = w[k];
            a20[k] = ffma2(x0, ww, a20[k]);
            a21[k] = ffma2(x1, ww, a21[k]);
        }
    }

    // ---- relu + layer 3: 16 -> 1 ----
    float s0 = sB3, s1 = sB3;
#pragma unroll
    for (int k = 0; k < 8; k++) {
        float lo, hi;
        unpack2(a20[k], lo, hi);
        s0 += fmaxf(lo, 0.0f) * sW3[2 * k] + fmaxf(hi, 0.0f) * sW3[2 * k + 1];
        unpack2(a21[k], lo, hi);
        s1 += fmaxf(lo, 0.0f) * sW3[2 * k] + fmaxf(hi, 0.0f) * sW3[2 * k + 1];
    }

    out[r0]     = s0;
    out[r0 + 1] = s1;
}

extern "C" void kernel_launch(void* const* d_in, const int* in_sizes, int n_in,
                              void* d_out, int out_size)
{
    const float* x_q      = (const float*)d_in[0];
    const float* x_c      = (const float*)d_in[1];
    const float* q_params = (const float*)d_in[2];
    const float* W1       = (const float*)d_in[3];
    const float* b1       = (const float*)d_in[4];
    const float* W2       = (const float*)d_in[5];
    const float* b2       = (const float*)d_in[6];
    const float* W3       = (const float*)d_in[7];
    const float* b3       = (const float*)d_in[8];
    float* out = (float*)d_out;

    int B = in_sizes[0] / 7;                 // x_q is (B, 7)
    int pairs = (B + 1) / 2;
    int grid = (pairs + TPB - 1) / TPB;

    hybrid_mlp_kernel<<<grid, TPB>>>(x_q, x_c, q_params, W1, b1, W2, b2, W3, b3,
                                     out, B);
}

// round 3
// speedup vs baseline: 1.1659x; 1.1659x over previous
#include <cuda_runtime.h>

// HybridSurvivalQ: q_out = prod_{q=1..6} cos(x_q[q]+theta[q]); then 65->32->16->1
// MLP with ReLU. 4 rows per thread (FMA:LDS = 4:1 so the smem crossbar is off the
// critical path), packed fma.rn.f32x2 accumulators, weights broadcast from SMEM.

#define TPB 128
#define R   4

typedef unsigned long long u64;

__device__ __forceinline__ u64 pack2(float lo, float hi) {
    u64 r;
    asm("mov.b64 %0, {%1, %2};" : "=l"(r) : "f"(lo), "f"(hi));
    return r;
}
__device__ __forceinline__ void unpack2(u64 v, float& lo, float& hi) {
    asm("mov.b64 {%0, %1}, %2;" : "=f"(lo), "=f"(hi) : "l"(v));
}
__device__ __forceinline__ u64 ffma2(u64 a, u64 b, u64 c) {
    u64 d;
    asm("fma.rn.f32x2 %0, %1, %2, %3;" : "=l"(d) : "l"(a), "l"(b), "l"(c));
    return d;
}

__global__ __launch_bounds__(TPB, 2)
void hybrid_mlp_kernel(const float* __restrict__ x_q,
                       const float* __restrict__ x_c,
                       const float* __restrict__ q_params,
                       const float* __restrict__ W1,
                       const float* __restrict__ b1,
                       const float* __restrict__ W2,
                       const float* __restrict__ b2,
                       const float* __restrict__ W3,
                       const float* __restrict__ b3,
                       float* __restrict__ out,
                       int B)
{
    __shared__ __align__(16) float sW1[65 * 32];
    __shared__ __align__(16) float sW2[32 * 16];
    __shared__ __align__(16) float sW3[16];
    __shared__ __align__(16) float sB1[32];
    __shared__ __align__(16) float sB2[16];
    __shared__ float sQP[8];
    __shared__ float sB3;

    for (int i = threadIdx.x; i < 65 * 32; i += TPB) sW1[i] = W1[i];
    for (int i = threadIdx.x; i < 32 * 16; i += TPB) sW2[i] = W2[i];
    if (threadIdx.x < 16) sW3[threadIdx.x] = W3[threadIdx.x];
    if (threadIdx.x < 32) sB1[threadIdx.x] = b1[threadIdx.x];
    if (threadIdx.x < 16) sB2[threadIdx.x] = b2[threadIdx.x];
    if (threadIdx.x < 7)  sQP[threadIdx.x] = q_params[threadIdx.x];
    if (threadIdx.x == 0) sB3 = b3[0];
    __syncthreads();

    long long gtid = (long long)blockIdx.x * TPB + threadIdx.x;
    int r0 = (int)(gtid * R);
    if (r0 >= B) return;

    // clamped row indices (safe for ragged tail; stores are guarded)
    int row[R];
#pragma unroll
    for (int r = 0; r < R; r++) {
        int rr = r0 + r;
        row[r] = rr < B ? rr : B - 1;
    }

    // ---- quantum part: q_out = prod_{q=1..6} cos(x_q[q] + theta[q]) ----
    float qv[R];
#pragma unroll
    for (int r = 0; r < R; r++) {
        const float* xq = x_q + (long long)row[r] * 7;
        float p = 1.0f;
#pragma unroll
        for (int k = 1; k < 7; k++) p *= __cosf(xq[k] + sQP[k]);
        qv[r] = p;
    }

    // ---- layer 1: 65 -> 32, packed accumulators, R rows ----
    u64 acc[R][16];
    const u64* bb1 = (const u64*)sB1;
#pragma unroll
    for (int r = 0; r < R; r++)
#pragma unroll
        for (int k = 0; k < 16; k++) acc[r][k] = bb1[k];

    {   // input feature 0 = q_out
        u64 xp[R];
#pragma unroll
        for (int r = 0; r < R; r++) xp[r] = pack2(qv[r], qv[r]);
        const u64* w = (const u64*)sW1;
#pragma unroll
        for (int k = 0; k < 16; k++) {
            u64 ww = w[k];
#pragma unroll
            for (int r = 0; r < R; r++) acc[r][k] = ffma2(xp[r], ww, acc[r][k]);
        }
    }

    const float4* xc[R];
#pragma unroll
    for (int r = 0; r < R; r++)
        xc[r] = (const float4*)(x_c + (long long)row[r] * 64);

#pragma unroll 2
    for (int j4 = 0; j4 < 16; j4++) {
        float4 v[R];
#pragma unroll
        for (int r = 0; r < R; r++) v[r] = xc[r][j4];
#pragma unroll
        for (int s = 0; s < 4; s++) {
            u64 xp[R];
#pragma unroll
            for (int r = 0; r < R; r++) {
                float a = (s == 0) ? v[r].x : (s == 1) ? v[r].y : (s == 2) ? v[r].z : v[r].w;
                xp[r] = pack2(a, a);
            }
            int j = 1 + j4 * 4 + s;
            const u64* w = (const u64*)(sW1 + j * 32);
#pragma unroll
            for (int k = 0; k < 16; k++) {
                u64 ww = w[k];
#pragma unroll
                for (int r = 0; r < R; r++) acc[r][k] = ffma2(xp[r], ww, acc[r][k]);
            }
        }
    }

    // ---- relu + layer 2: 32 -> 16 (read relu'd halves straight from acc) ----
    u64 a2[R][8];
    const u64* bb2 = (const u64*)sB2;
#pragma unroll
    for (int r = 0; r < R; r++)
#pragma unroll
        for (int k = 0; k < 8; k++) a2[r][k] = bb2[k];

#pragma unroll
    for (int j = 0; j < 32; j++) {
        u64 xp[R];
#pragma unroll
        for (int r = 0; r < R; r++) {
            float lo, hi;
            unpack2(acc[r][j >> 1], lo, hi);
            float h = fmaxf((j & 1) ? hi : lo, 0.0f);
            xp[r] = pack2(h, h);
        }
        const u64* w = (const u64*)(sW2 + j * 16);
#pragma unroll
        for (int k = 0; k < 8; k++) {
            u64 ww = w[k];
#pragma unroll
            for (int r = 0; r < R; r++) a2[r][k] = ffma2(xp[r], ww, a2[r][k]);
        }
    }

    // ---- relu + layer 3: 16 -> 1 ----
    float s[R];
#pragma unroll
    for (int r = 0; r < R; r++) s[r] = sB3;
#pragma unroll
    for (int k = 0; k < 8; k++) {
        float w0 = sW3[2 * k], w1 = sW3[2 * k + 1];
#pragma unroll
        for (int r = 0; r < R; r++) {
            float lo, hi;
            unpack2(a2[r][k], lo, hi);
            s[r] += fmaxf(lo, 0.0f) * w0 + fmaxf(hi, 0.0f) * w1;
        }
    }

#pragma unroll
    for (int r = 0; r < R; r++)
        if (r0 + r < B) out[r0 + r] = s[r];
}

extern "C" void kernel_launch(void* const* d_in, const int* in_sizes, int n_in,
                              void* d_out, int out_size)
{
    const float* x_q      = (const float*)d_in[0];
    const float* x_c      = (const float*)d_in[1];
    const float* q_params = (const float*)d_in[2];
    const float* W1       = (const float*)d_in[3];
    const float* b1       = (const float*)d_in[4];
    const float* W2       = (const float*)d_in[5];
    const float* b2       = (const float*)d_in[6];
    const float* W3       = (const float*)d_in[7];
    const float* b3       = (const float*)d_in[8];
    float* out = (float*)d_out;

    int B = in_sizes[0] / 7;                 // x_q is (B, 7)
    long long rows_per_blk = (long long)TPB * R;
    int grid = (int)((B + rows_per_blk - 1) / rows_per_blk);

    hybrid_mlp_kernel<<<grid, TPB>>>(x_q, x_c, q_params, W1, b1, W2, b2, W3, b3,
                                     out, B);
}